// round 16
// baseline (speedup 1.0000x reference)
#include <cuda_runtime.h>
#include <math.h>

// StackGRU: B=64, T=1024, I=64, H=512, O=24
// Persistent cooperative kernel: 128 CTAs (1/SM), software grid barrier,
// all weights resident in SMEM, hidden state double-buffered in GMEM (L2).
//
// Per step:
//   phase 1: h1[t] = GRUcell(x_t, h1[t-1])        (1536 gate rows, len 576)
//            + out2 contribution for step t-1 (CTAs 24..47)
//   phase 2: h2[t] = GRUcell(h1[t], h2[t-1])      (1536 gate rows, len 1024)
//            + out1 contribution for step t   (CTAs 0..23)
// CTA c owns hidden units j = 4c..4c+3 (r,z,n gate rows each).
// Warp layout (8 warps): warp = (jl<<1)|half ; lane b = half*32+lane.

constexpr int BATCH = 64;
constexpr int SEQ   = 1024;
constexpr int INP   = 64;
constexpr int HID   = 512;
constexpr int OUTD  = 24;
constexpr int NCTA  = 128;   // HID / JPC ; <= SM count -> all co-resident
constexpr int JPC   = 4;     // hidden units per CTA
constexpr int NTHR  = 256;   // 8 warps

// ---------------- device-global scratch (no allocations allowed) ----------
__device__ float g_xT[SEQ][INP][BATCH];     // x transposed: [t][i][b]
__device__ float g_h1[2][HID][BATCH];       // double-buffered h1, [par][k][b]
__device__ float g_h2[2][HID][BATCH];
__device__ unsigned g_bar_count;            // zero-init at load; returns to 0
__device__ volatile unsigned g_bar_gen;     // monotonic generation counter

// ---------------- smem layout (persistent weights) ------------------------
struct __align__(16) Smem {
  float w1 [JPC][3][HID];   // w_hh1 rows (r,z,n) for this CTA's 4 j's
  float w2i[JPC][3][HID];   // w_ih2 rows
  float w2h[JPC][3][HID];   // w_hh2 rows
  float wx [JPC][3][INP];   // w_ih1 rows
  float wo [HID];           // w_o1 row (cta<24) or w_o2 row (24<=cta<48)
  float b1rz[JPC][2];       // b_ih1+b_hh1 for r,z
  float b1ni[JPC];          // b_ih1 n-part
  float b1nh[JPC];          // b_hh1 n-part
  float b2rz[JPC][2];
  float b2ni[JPC];
  float b2nh[JPC];
  float bo;                 // output bias for this CTA's o-row
};

// ---------------- helpers --------------------------------------------------
__global__ void transpose_x_kernel(const float* __restrict__ x) {
  const int n = BATCH * SEQ * INP;
  for (int idx = blockIdx.x * blockDim.x + threadIdx.x; idx < n;
       idx += gridDim.x * blockDim.x) {
    int i = idx & (INP - 1);          // x layout [b][t][i]
    int t = (idx >> 6) & (SEQ - 1);
    int b = idx >> 16;                // / (INP*SEQ) = / 65536
    g_xT[t][i][b] = x[idx];
  }
}

// Sense-reversing grid barrier. __threadfence() (gpu scope) both orders the
// h-state stores and invalidates L1D (CCTL.IVALL), so post-barrier reads of
// other SMs' h writes are coherent.
__device__ __forceinline__ void grid_sync() {
  __syncthreads();
  if (threadIdx.x == 0) {
    unsigned gen = g_bar_gen;
    __threadfence();
    if (atomicAdd(&g_bar_count, 1u) == (unsigned)(NCTA - 1)) {
      g_bar_count = 0u;
      __threadfence();
      g_bar_gen = gen + 1u;
    } else {
      while (g_bar_gen == gen) { }
    }
    __threadfence();
  }
  __syncthreads();
}

__device__ __forceinline__ float sigmoidf_(float v) {
  return 1.0f / (1.0f + expf(-v));
}

// Accumulate 3 gate-row dot products against h[k][b] for this lane's batch b.
// Weights come from SMEM (LDS.128 broadcast), h from GMEM (coalesced LDG.32).
template <int N4>
__device__ __forceinline__ void dot3_acc(const float4* __restrict__ wa,
                                         const float4* __restrict__ wb,
                                         const float4* __restrict__ wc,
                                         const float* __restrict__ hp,
                                         float& a0, float& a1, float& a2) {
#pragma unroll 4
  for (int kk = 0; kk < N4; ++kk) {
    float4 w0 = wa[kk], w1 = wb[kk], w2 = wc[kk];
    float h0 = hp[0], h1 = hp[BATCH], h2 = hp[2 * BATCH], h3 = hp[3 * BATCH];
    hp += 4 * BATCH;
    a0 = fmaf(w0.x, h0, a0); a0 = fmaf(w0.y, h1, a0);
    a0 = fmaf(w0.z, h2, a0); a0 = fmaf(w0.w, h3, a0);
    a1 = fmaf(w1.x, h0, a1); a1 = fmaf(w1.y, h1, a1);
    a1 = fmaf(w1.z, h2, a1); a1 = fmaf(w1.w, h3, a1);
    a2 = fmaf(w2.x, h0, a2); a2 = fmaf(w2.y, h1, a2);
    a2 = fmaf(w2.z, h2, a2); a2 = fmaf(w2.w, h3, a2);
  }
}

template <int N4>
__device__ __forceinline__ float dot1(const float4* __restrict__ w,
                                      const float* __restrict__ hp) {
  float a = 0.f;
#pragma unroll 4
  for (int kk = 0; kk < N4; ++kk) {
    float4 w0 = w[kk];
    float h0 = hp[0], h1 = hp[BATCH], h2 = hp[2 * BATCH], h3 = hp[3 * BATCH];
    hp += 4 * BATCH;
    a = fmaf(w0.x, h0, a); a = fmaf(w0.y, h1, a);
    a = fmaf(w0.z, h2, a); a = fmaf(w0.w, h3, a);
  }
  return a;
}

// ---------------- main persistent kernel ----------------------------------
__global__ void __launch_bounds__(NTHR, 1)
gru_kernel(const float* __restrict__ w_ih1, const float* __restrict__ w_hh1,
           const float* __restrict__ b_ih1, const float* __restrict__ b_hh1,
           const float* __restrict__ w_ih2, const float* __restrict__ w_hh2,
           const float* __restrict__ b_ih2, const float* __restrict__ b_hh2,
           const float* __restrict__ w_o1,  const float* __restrict__ b_o1,
           const float* __restrict__ w_o2,  const float* __restrict__ b_o2,
           float* __restrict__ out) {
  extern __shared__ char smem_raw[];
  Smem& S = *reinterpret_cast<Smem*>(smem_raw);

  const int tid = threadIdx.x;
  const int cta = blockIdx.x;
  const int j0  = cta * JPC;

  // ---- load weights into SMEM (once per launch) ----
  for (int idx = tid; idx < JPC * 3 * HID; idx += NTHR) {
    int k  = idx & (HID - 1);
    int g  = (idx >> 9) % 3;
    int jl = idx / (3 * HID);
    int row = g * HID + j0 + jl;
    S.w1 [jl][g][k] = w_hh1[row * HID + k];
    S.w2i[jl][g][k] = w_ih2[row * HID + k];
    S.w2h[jl][g][k] = w_hh2[row * HID + k];
  }
  for (int idx = tid; idx < JPC * 3 * INP; idx += NTHR) {
    int k  = idx & (INP - 1);
    int g  = (idx >> 6) % 3;
    int jl = idx / (3 * INP);
    S.wx[jl][g][k] = w_ih1[(g * HID + j0 + jl) * INP + k];
  }
  if (cta < OUTD) {
    for (int k = tid; k < HID; k += NTHR) S.wo[k] = w_o1[cta * HID + k];
    if (tid == 0) S.bo = b_o1[cta];
  } else if (cta < 2 * OUTD) {
    int o = cta - OUTD;
    for (int k = tid; k < HID; k += NTHR) S.wo[k] = w_o2[o * HID + k];
    if (tid == 0) S.bo = b_o2[o];
  }
  if (tid < JPC) {
    int j = j0 + tid;
    S.b1rz[tid][0] = b_ih1[j] + b_hh1[j];
    S.b1rz[tid][1] = b_ih1[HID + j] + b_hh1[HID + j];
    S.b1ni[tid] = b_ih1[2 * HID + j];
    S.b1nh[tid] = b_hh1[2 * HID + j];
    S.b2rz[tid][0] = b_ih2[j] + b_hh2[j];
    S.b2rz[tid][1] = b_ih2[HID + j] + b_hh2[HID + j];
    S.b2ni[tid] = b_ih2[2 * HID + j];
    S.b2nh[tid] = b_hh2[2 * HID + j];
  }
  // ---- zero both parities of both hidden states ----
  for (int idx = cta * NTHR + tid; idx < 2 * HID * BATCH; idx += NCTA * NTHR) {
    (&g_h1[0][0][0])[idx] = 0.f;
    (&g_h2[0][0][0])[idx] = 0.f;
  }
  __syncthreads();
  grid_sync();   // h zero-init visible everywhere

  const int warp = tid >> 5, lane = tid & 31;
  const int jl   = warp >> 1;
  const int b    = ((warp & 1) << 5) + lane;   // this lane's batch index
  const int j    = j0 + jl;
  const bool out1_duty = (cta < OUTD) && (jl == 0);
  const bool out2_duty = (cta >= OUTD) && (cta < 2 * OUTD) && (jl == 0);
  const int  o2        = cta - OUTD;

  const float4* w1r = reinterpret_cast<const float4*>(&S.w1 [jl][0][0]);
  const float4* w1z = reinterpret_cast<const float4*>(&S.w1 [jl][1][0]);
  const float4* w1n = reinterpret_cast<const float4*>(&S.w1 [jl][2][0]);
  const float4* wxr = reinterpret_cast<const float4*>(&S.wx [jl][0][0]);
  const float4* wxz = reinterpret_cast<const float4*>(&S.wx [jl][1][0]);
  const float4* wxn = reinterpret_cast<const float4*>(&S.wx [jl][2][0]);
  const float4* w2ir = reinterpret_cast<const float4*>(&S.w2i[jl][0][0]);
  const float4* w2iz = reinterpret_cast<const float4*>(&S.w2i[jl][1][0]);
  const float4* w2in = reinterpret_cast<const float4*>(&S.w2i[jl][2][0]);
  const float4* w2hr = reinterpret_cast<const float4*>(&S.w2h[jl][0][0]);
  const float4* w2hz = reinterpret_cast<const float4*>(&S.w2h[jl][1][0]);
  const float4* w2hn = reinterpret_cast<const float4*>(&S.w2h[jl][2][0]);
  const float4* wo4  = reinterpret_cast<const float4*>(&S.wo[0]);

  for (int t = 0; t < SEQ; ++t) {
    const int cur = t & 1, prv = cur ^ 1;

    // ================= phase 1: layer-1 gates =================
    float ar = 0.f, az = 0.f, anh = 0.f, anx = 0.f;
    dot3_acc<HID / 4>(w1r, w1z, w1n, &g_h1[prv][0][b], ar, az, anh);
    dot3_acc<INP / 4>(wxr, wxz, wxn, &g_xT[t][0][b],   ar, az, anx);
    {
      float r = sigmoidf_(ar + S.b1rz[jl][0]);
      float z = sigmoidf_(az + S.b1rz[jl][1]);
      float n = tanhf(anx + S.b1ni[jl] + r * (anh + S.b1nh[jl]));
      float hold = g_h1[prv][j][b];
      g_h1[cur][j][b] = (1.f - z) * n + z * hold;
    }
    // out2 contribution for step t-1: tanh(h2[t-1] . w_o2[o2]) added to out
    if (out2_duty && t > 0) {
      float acc = dot1<HID / 4>(wo4, &g_h2[prv][0][b]);
      float* p = &out[(b * SEQ + (t - 1)) * OUTD + o2];
      *p += tanhf(acc + S.bo);
    }
    grid_sync();   // h1[t] complete & visible

    // ================= phase 2: layer-2 gates =================
    float ar2 = 0.f, az2 = 0.f, ain = 0.f, ahn = 0.f;
    dot3_acc<HID / 4>(w2ir, w2iz, w2in, &g_h1[cur][0][b], ar2, az2, ain);
    dot3_acc<HID / 4>(w2hr, w2hz, w2hn, &g_h2[prv][0][b], ar2, az2, ahn);
    {
      float r = sigmoidf_(ar2 + S.b2rz[jl][0]);
      float z = sigmoidf_(az2 + S.b2rz[jl][1]);
      float n = tanhf(ain + S.b2ni[jl] + r * (ahn + S.b2nh[jl]));
      float hold = g_h2[prv][j][b];
      g_h2[cur][j][b] = (1.f - z) * n + z * hold;
    }
    // out1 contribution for step t: overwrites poisoned out buffer
    if (out1_duty) {
      float acc = dot1<HID / 4>(wo4, &g_h1[cur][0][b]);
      out[(b * SEQ + t) * OUTD + cta] = tanhf(acc + S.bo);
    }
    grid_sync();   // h2[t] complete & visible
  }

  // epilogue: out2 for the final step (h2[T-1] lives in parity (T-1)&1 == 1)
  if (out2_duty) {
    float acc = dot1<HID / 4>(wo4, &g_h2[1][0][b]);
    out[(b * SEQ + (SEQ - 1)) * OUTD + o2] += tanhf(acc + S.bo);
  }
}

// ---------------- launch ---------------------------------------------------
extern "C" void kernel_launch(void* const* d_in, const int* in_sizes, int n_in,
                              void* d_out, int out_size) {
  const float* x     = (const float*)d_in[0];
  const float* w_ih1 = (const float*)d_in[1];
  const float* w_hh1 = (const float*)d_in[2];
  const float* b_ih1 = (const float*)d_in[3];
  const float* b_hh1 = (const float*)d_in[4];
  const float* w_ih2 = (const float*)d_in[5];
  const float* w_hh2 = (const float*)d_in[6];
  const float* b_ih2 = (const float*)d_in[7];
  const float* b_hh2 = (const float*)d_in[8];
  const float* w_o1  = (const float*)d_in[9];
  const float* b_o1  = (const float*)d_in[10];
  const float* w_o2  = (const float*)d_in[11];
  const float* b_o2  = (const float*)d_in[12];
  float* out = (float*)d_out;

  transpose_x_kernel<<<256, 256>>>(x);

  cudaFuncSetAttribute((const void*)gru_kernel,
                       cudaFuncAttributeMaxDynamicSharedMemorySize,
                       (int)sizeof(Smem));
  gru_kernel<<<NCTA, NTHR, sizeof(Smem)>>>(w_ih1, w_hh1, b_ih1, b_hh1,
                                           w_ih2, w_hh2, b_ih2, b_hh2,
                                           w_o1, b_o1, w_o2, b_o2, out);
}

// round 17
// speedup vs baseline: 1.8479x; 1.8479x over previous
#include <cuda_runtime.h>
#include <cuda_pipeline.h>
#include <math.h>

// StackGRU: B=64, T=1024, I=64, H=512, O=24
// Persistent cooperative kernel, 128 CTAs (1/SM), grid barrier between phases.
// R17: h staged through SMEM in 256x64 chunks with cp.async double-buffering;
// all dot-product reads come from SMEM (LDS), killing the LDG issue floor and
// the post-fence L2 latency exposure. Phase-2's h1cur staging is reused as
// phase-1's h1prev next step (same data) -> no reload.

constexpr int BATCH = 64;
constexpr int SEQ   = 1024;
constexpr int INP   = 64;
constexpr int HID   = 512;
constexpr int OUTD  = 24;
constexpr int NCTA  = 128;
constexpr int JPC   = 4;      // hidden units per CTA (12 gate rows)
constexpr int NTHR  = 256;    // 8 warps: warp=(jl<<1)|half, lane b=half*32+lane
constexpr int CHK   = 256;    // k-chunk size (CHK*BATCH floats = 64KB)

// ---------------- device-global scratch ------------------------------------
__device__ float g_xT[SEQ][INP][BATCH];   // [t][i][b]
__device__ float g_h1[2][HID][BATCH];     // [parity][k][b]
__device__ float g_h2[2][HID][BATCH];
__device__ unsigned g_bar_count;
__device__ volatile unsigned g_bar_gen;

// ---------------- smem -----------------------------------------------------
struct __align__(16) Smem {
  float w1 [JPC][3][HID];      // w_hh1 rows (r,z,n)
  float w2i[JPC][3][HID];      // w_ih2 rows
  float w2h[JPC][3][HID];      // w_hh2 rows
  float wx [JPC][3][INP];      // w_ih1 rows
  float wo [HID];              // out-row for duty CTAs (else zeros)
  float B  [2][CHK * BATCH];   // staging buffers (64KB each)
  float BX [INP * BATCH];      // x_t staging (16KB)
  float Pout[JPC][BATCH];      // out-dot partials (k-quarter per jl)
  float b1rz[JPC][2], b1ni[JPC], b1nh[JPC];
  float b2rz[JPC][2], b2ni[JPC], b2nh[JPC];
  float bo;
};

// ---------------- helpers --------------------------------------------------
__global__ void transpose_x_kernel(const float* __restrict__ x) {
  const int n = BATCH * SEQ * INP;
  for (int idx = blockIdx.x * blockDim.x + threadIdx.x; idx < n;
       idx += gridDim.x * blockDim.x) {
    int i = idx & (INP - 1);          // x layout [b][t][i]
    int t = (idx >> 6) & (SEQ - 1);
    int b = idx >> 16;
    g_xT[t][i][b] = x[idx];
  }
}

__device__ __forceinline__ void grid_sync() {
  __syncthreads();
  if (threadIdx.x == 0) {
    unsigned gen = g_bar_gen;
    __threadfence();
    if (atomicAdd(&g_bar_count, 1u) == (unsigned)(NCTA - 1)) {
      g_bar_count = 0u;
      __threadfence();
      g_bar_gen = gen + 1u;
    } else {
      while (g_bar_gen == gen) { }
    }
    __threadfence();
  }
  __syncthreads();
}

__device__ __forceinline__ float sigmoidf_(float v) {
  return 1.0f / (1.0f + expf(-v));
}

// stage a contiguous 64KB [CHK][BATCH] block: 16 x 16B per thread
__device__ __forceinline__ void stage_chunk(float* dst, const float* src,
                                            int tid) {
  float4* d = reinterpret_cast<float4*>(dst);
  const float4* s = reinterpret_cast<const float4*>(src);
#pragma unroll
  for (int i = 0; i < (CHK * BATCH / 4) / NTHR; ++i)
    __pipeline_memcpy_async(&d[tid + i * NTHR], &s[tid + i * NTHR], 16);
}
// stage the 16KB x block: 4 x 16B per thread
__device__ __forceinline__ void stage_x(float* dst, const float* src, int tid) {
  float4* d = reinterpret_cast<float4*>(dst);
  const float4* s = reinterpret_cast<const float4*>(src);
#pragma unroll
  for (int i = 0; i < (INP * BATCH / 4) / NTHR; ++i)
    __pipeline_memcpy_async(&d[tid + i * NTHR], &s[tid + i * NTHR], 16);
}

// 3-gate dot over NK4*4 k's read from SMEM. hp = &buf[0][b], row stride 64.
template <int NK4>
__device__ __forceinline__ void dot3_s(const float4* __restrict__ wr,
                                       const float4* __restrict__ wz,
                                       const float4* __restrict__ wn,
                                       const float* __restrict__ hp,
                                       float& a0, float& a1, float& a2) {
#pragma unroll 4
  for (int kk = 0; kk < NK4; ++kk) {
    float4 w0 = wr[kk], w1 = wz[kk], w2 = wn[kk];
    float h0 = hp[0], h1 = hp[64], h2 = hp[128], h3 = hp[192];
    hp += 256;
    a0 = fmaf(w0.x, h0, a0); a0 = fmaf(w0.y, h1, a0);
    a0 = fmaf(w0.z, h2, a0); a0 = fmaf(w0.w, h3, a0);
    a1 = fmaf(w1.x, h0, a1); a1 = fmaf(w1.y, h1, a1);
    a1 = fmaf(w1.z, h2, a1); a1 = fmaf(w1.w, h3, a1);
    a2 = fmaf(w2.x, h0, a2); a2 = fmaf(w2.y, h1, a2);
    a2 = fmaf(w2.z, h2, a2); a2 = fmaf(w2.w, h3, a2);
  }
}

// out-row quarter dot: 64 k's from SMEM
__device__ __forceinline__ float dot1_q(const float4* __restrict__ w,
                                        const float* __restrict__ hp, float a) {
#pragma unroll 4
  for (int kk = 0; kk < 16; ++kk) {
    float4 w0 = w[kk];
    a = fmaf(w0.x, hp[0], a);   a = fmaf(w0.y, hp[64], a);
    a = fmaf(w0.z, hp[128], a); a = fmaf(w0.w, hp[192], a);
    hp += 256;
  }
  return a;
}

// ---------------- main persistent kernel -----------------------------------
__global__ void __launch_bounds__(NTHR, 1)
gru_kernel(const float* __restrict__ w_ih1, const float* __restrict__ w_hh1,
           const float* __restrict__ b_ih1, const float* __restrict__ b_hh1,
           const float* __restrict__ w_ih2, const float* __restrict__ w_hh2,
           const float* __restrict__ b_ih2, const float* __restrict__ b_hh2,
           const float* __restrict__ w_o1,  const float* __restrict__ b_o1,
           const float* __restrict__ w_o2,  const float* __restrict__ b_o2,
           float* __restrict__ out) {
  extern __shared__ char smem_raw[];
  Smem& S = *reinterpret_cast<Smem*>(smem_raw);

  const int tid = threadIdx.x;
  const int cta = blockIdx.x;
  const int j0  = cta * JPC;

  // ---- load weights into SMEM ----
  for (int idx = tid; idx < JPC * 3 * HID; idx += NTHR) {
    int k  = idx & (HID - 1);
    int g  = (idx >> 9) % 3;
    int jl = idx / (3 * HID);
    int row = g * HID + j0 + jl;
    S.w1 [jl][g][k] = w_hh1[row * HID + k];
    S.w2i[jl][g][k] = w_ih2[row * HID + k];
    S.w2h[jl][g][k] = w_hh2[row * HID + k];
  }
  for (int idx = tid; idx < JPC * 3 * INP; idx += NTHR) {
    int k  = idx & (INP - 1);
    int g  = (idx >> 6) % 3;
    int jl = idx / (3 * INP);
    S.wx[jl][g][k] = w_ih1[(g * HID + j0 + jl) * INP + k];
  }
  for (int k = tid; k < HID; k += NTHR) {
    float w = 0.f;
    if (cta < OUTD)          w = w_o1[cta * HID + k];
    else if (cta < 2 * OUTD) w = w_o2[(cta - OUTD) * HID + k];
    S.wo[k] = w;
  }
  if (tid == 0)
    S.bo = (cta < OUTD) ? b_o1[cta]
         : (cta < 2 * OUTD) ? b_o2[cta - OUTD] : 0.f;
  if (tid < JPC) {
    int j = j0 + tid;
    S.b1rz[tid][0] = b_ih1[j] + b_hh1[j];
    S.b1rz[tid][1] = b_ih1[HID + j] + b_hh1[HID + j];
    S.b1ni[tid] = b_ih1[2 * HID + j];
    S.b1nh[tid] = b_hh1[2 * HID + j];
    S.b2rz[tid][0] = b_ih2[j] + b_hh2[j];
    S.b2rz[tid][1] = b_ih2[HID + j] + b_hh2[HID + j];
    S.b2ni[tid] = b_ih2[2 * HID + j];
    S.b2nh[tid] = b_hh2[2 * HID + j];
  }
  // ---- zero both parities of both hidden states ----
  for (int idx = cta * NTHR + tid; idx < 2 * HID * BATCH; idx += NCTA * NTHR) {
    (&g_h1[0][0][0])[idx] = 0.f;
    (&g_h2[0][0][0])[idx] = 0.f;
  }
  __syncthreads();
  grid_sync();   // zero-init globally visible

  const int warp = tid >> 5, lane = tid & 31;
  const int jl   = warp >> 1;
  const int b    = ((warp & 1) << 5) + lane;
  const int j    = j0 + jl;
  const int duty = (cta < OUTD) ? 1 : (cta < 2 * OUTD) ? 2 : 0;
  const int orow = (duty == 1) ? cta : cta - OUTD;

  const float4* w1r[2]  = {(const float4*)&S.w1 [jl][0][0], (const float4*)&S.w1 [jl][0][CHK]};
  const float4* w1z[2]  = {(const float4*)&S.w1 [jl][1][0], (const float4*)&S.w1 [jl][1][CHK]};
  const float4* w1n[2]  = {(const float4*)&S.w1 [jl][2][0], (const float4*)&S.w1 [jl][2][CHK]};
  const float4* w2ir[2] = {(const float4*)&S.w2i[jl][0][0], (const float4*)&S.w2i[jl][0][CHK]};
  const float4* w2iz[2] = {(const float4*)&S.w2i[jl][1][0], (const float4*)&S.w2i[jl][1][CHK]};
  const float4* w2in[2] = {(const float4*)&S.w2i[jl][2][0], (const float4*)&S.w2i[jl][2][CHK]};
  const float4* w2hr[2] = {(const float4*)&S.w2h[jl][0][0], (const float4*)&S.w2h[jl][0][CHK]};
  const float4* w2hz[2] = {(const float4*)&S.w2h[jl][1][0], (const float4*)&S.w2h[jl][1][CHK]};
  const float4* w2hn[2] = {(const float4*)&S.w2h[jl][2][0], (const float4*)&S.w2h[jl][2][CHK]};
  const float4* wxr = (const float4*)&S.wx[jl][0][0];
  const float4* wxz = (const float4*)&S.wx[jl][1][0];
  const float4* wxn = (const float4*)&S.wx[jl][2][0];
  const float4* woq[2] = {(const float4*)&S.wo[jl * 64],
                          (const float4*)&S.wo[CHK + jl * 64]};
  const int qoff = jl * 64 * BATCH + b;   // quarter offset inside a chunk

  // ---- prologue: stage h1prev (zeros) chunks + x[0] ----
  stage_chunk(S.B[0], &g_h1[1][0][0],        tid); __pipeline_commit();
  stage_chunk(S.B[1], &g_h1[1][CHK][0],      tid); __pipeline_commit();
  stage_x   (S.BX,    &g_xT[0][0][0],        tid); __pipeline_commit();
  __pipeline_wait_prior(0);
  __syncthreads();

  for (int t = 0; t < SEQ; ++t) {
    const int cur = t & 1, prv = cur ^ 1;

    // ===== phase 1: layer-1 gates (B0/B1 hold h1prev, BX holds x_t) =====
    float hold1 = g_h1[prv][j][b];
    float ar = 0.f, az = 0.f, anh = 0.f, anx = 0.f;
    dot3_s<CHK / 4>(w1r[0], w1z[0], w1n[0], &S.B[0][b], ar, az, anh);
    __syncthreads();
    stage_chunk(S.B[0], &g_h2[prv][0][0], tid);  __pipeline_commit(); // g1
    dot3_s<CHK / 4>(w1r[1], w1z[1], w1n[1], &S.B[1][b], ar, az, anh);
    __syncthreads();
    stage_chunk(S.B[1], &g_h2[prv][CHK][0], tid); __pipeline_commit(); // g2
    dot3_s<INP / 4>(wxr, wxz, wxn, &S.BX[b], ar, az, anx);
    __syncthreads();
    if (t + 1 < SEQ) stage_x(S.BX, &g_xT[t + 1][0][0], tid);
    __pipeline_commit();                                              // g3
    {
      float r = sigmoidf_(ar + S.b1rz[jl][0]);
      float z = sigmoidf_(az + S.b1rz[jl][1]);
      float n = tanhf(anx + S.b1ni[jl] + r * (anh + S.b1nh[jl]));
      g_h1[cur][j][b] = (1.f - z) * n + z * hold1;
    }
    grid_sync();   // h1[t] complete & visible everywhere

    // ===== phase 2: layer-2 gates; B0/B1 get h2prv then h1cur =====
    float hold2 = g_h2[prv][j][b];
    float ar2 = 0.f, az2 = 0.f, ain = 0.f, ahn = 0.f, ao = 0.f;

    __pipeline_wait_prior(2); __syncthreads();     // g1 (h2prv0) ready
    dot3_s<CHK / 4>(w2hr[0], w2hz[0], w2hn[0], &S.B[0][b], ar2, az2, ahn);
    if (duty == 2) ao = dot1_q(woq[0], &S.B[0][qoff], ao);
    __syncthreads();
    stage_chunk(S.B[0], &g_h1[cur][0][0], tid);  __pipeline_commit(); // g4

    __pipeline_wait_prior(2); __syncthreads();     // g2 (h2prv1) ready
    dot3_s<CHK / 4>(w2hr[1], w2hz[1], w2hn[1], &S.B[1][b], ar2, az2, ahn);
    if (duty == 2) ao = dot1_q(woq[1], &S.B[1][qoff], ao);
    __syncthreads();
    stage_chunk(S.B[1], &g_h1[cur][CHK][0], tid); __pipeline_commit(); // g5

    __pipeline_wait_prior(1); __syncthreads();     // g3,g4 done (h1cur0)
    dot3_s<CHK / 4>(w2ir[0], w2iz[0], w2in[0], &S.B[0][b], ar2, az2, ain);
    if (duty == 1) ao = dot1_q(woq[0], &S.B[0][qoff], ao);

    __pipeline_wait_prior(0); __syncthreads();     // g5 done (h1cur1)
    dot3_s<CHK / 4>(w2ir[1], w2iz[1], w2in[1], &S.B[1][b], ar2, az2, ain);
    if (duty == 1) ao = dot1_q(woq[1], &S.B[1][qoff], ao);
    {
      float r = sigmoidf_(ar2 + S.b2rz[jl][0]);
      float z = sigmoidf_(az2 + S.b2rz[jl][1]);
      float n = tanhf(ain + S.b2ni[jl] + r * (ahn + S.b2nh[jl]));
      g_h2[cur][j][b] = (1.f - z) * n + z * hold2;
    }
    // out-row reduction (4 k-quarter partials per batch)
    if (duty) S.Pout[jl][b] = ao;
    __syncthreads();
    if (duty && tid < BATCH) {
      float o = S.Pout[0][tid] + S.Pout[1][tid] + S.Pout[2][tid] +
                S.Pout[3][tid];
      float v = tanhf(o + S.bo);
      if (duty == 1) {
        out[(tid * SEQ + t) * OUTD + orow] = v;          // overwrite poison
      } else if (t > 0) {
        out[(tid * SEQ + (t - 1)) * OUTD + orow] += v;   // out2 for t-1
      }
    }
    grid_sync();   // h2[t] visible; B0/B1 now hold h1prev for step t+1
  }

  // epilogue: out2 for final step from g_h2[parity 1]
  if (duty == 2) {
    float ao = 0.f;
    const float* hp = &g_h2[1][jl * 128][b];
    const float* wp = &S.wo[jl * 128];
#pragma unroll 4
    for (int k = 0; k < 128; ++k) ao = fmaf(wp[k], hp[k * BATCH], ao);
    S.Pout[jl][b] = ao;
    __syncthreads();
    if (tid < BATCH) {
      float o = S.Pout[0][tid] + S.Pout[1][tid] + S.Pout[2][tid] +
                S.Pout[3][tid];
      out[(tid * SEQ + (SEQ - 1)) * OUTD + orow] += tanhf(o + S.bo);
    }
  }
}

// ---------------- launch ---------------------------------------------------
extern "C" void kernel_launch(void* const* d_in, const int* in_sizes, int n_in,
                              void* d_out, int out_size) {
  const float* x     = (const float*)d_in[0];
  const float* w_ih1 = (const float*)d_in[1];
  const float* w_hh1 = (const float*)d_in[2];
  const float* b_ih1 = (const float*)d_in[3];
  const float* b_hh1 = (const float*)d_in[4];
  const float* w_ih2 = (const float*)d_in[5];
  const float* w_hh2 = (const float*)d_in[6];
  const float* b_ih2 = (const float*)d_in[7];
  const float* b_hh2 = (const float*)d_in[8];
  const float* w_o1  = (const float*)d_in[9];
  const float* b_o1  = (const float*)d_in[10];
  const float* w_o2  = (const float*)d_in[11];
  const float* b_o2  = (const float*)d_in[12];
  float* out = (float*)d_out;

  transpose_x_kernel<<<256, 256>>>(x);

  cudaFuncSetAttribute((const void*)gru_kernel,
                       cudaFuncAttributeMaxDynamicSharedMemorySize,
                       (int)sizeof(Smem));
  gru_kernel<<<NCTA, NTHR, sizeof(Smem)>>>(w_ih1, w_hh1, b_ih1, b_hh1,
                                           w_ih2, w_hh2, b_ih2, b_hh2,
                                           w_o1, b_o1, w_o2, b_o2, out);
}